// round 6
// baseline (speedup 1.0000x reference)
#include <cuda_runtime.h>
#include <cuda_bf16.h>
#include <cuda_fp16.h>
#include <stdint.h>

#define NN     100000
#define EE     1600000
#define IND    165
#define HID    64

// Scratch (device globals — no allocation allowed)
__device__ __align__(16) unsigned short g_y[NN * HID];  // fp16 message buffer
__device__ float g_h[NN * HID];       // root path / layer output (fp32)
__device__ int   g_deg[NN];           // in-degree (int)
__device__ int   g_off[NN + 1];       // CSR row offsets
__device__ int   g_cursor[NN];        // bucket-fill cursors
__device__ int   g_csr[EE];           // CSR column (src) indices
__device__ int   g_bsum[128];         // scan block sums

// Precomputed bf16-split weight tiles, MMA-ready layout [128 cols][W k2-words]
__device__ __align__(16) uint32_t g_w1h[128 * 92];
__device__ __align__(16) uint32_t g_w1l[128 * 92];
__device__ __align__(16) uint32_t g_w2h[128 * 36];
__device__ __align__(16) uint32_t g_w2l[128 * 36];

// ---------------------------------------------------------------------------
#define MMA_BF16(d, a, b0, b1)                                                 \
  asm volatile(                                                                \
      "mma.sync.aligned.m16n8k16.row.col.f32.bf16.bf16.f32 "                   \
      "{%0,%1,%2,%3},{%4,%5,%6,%7},{%8,%9},{%0,%1,%2,%3};"                     \
      : "+f"(d[0]), "+f"(d[1]), "+f"(d[2]), "+f"(d[3])                         \
      : "r"(a[0]), "r"(a[1]), "r"(a[2]), "r"(a[3]), "r"(b0), "r"(b1))

__device__ __forceinline__ void ldsm_x4(uint32_t* r, uint32_t addr)
{
    asm volatile("ldmatrix.sync.aligned.m8n8.x4.shared.b16 {%0,%1,%2,%3}, [%4];"
                 : "=r"(r[0]), "=r"(r[1]), "=r"(r[2]), "=r"(r[3]) : "r"(addr));
}

// ---------------------------------------------------------------------------
// Weight tile precompute (split bf16 hi/lo, transposed k-pair packed layout)
// ---------------------------------------------------------------------------
template <int K, int W>
__device__ __forceinline__ void prep_one(const float* Wl, const float* Wr,
                                         uint32_t* dh, uint32_t* dl, int tid0, int stride)
{
    for (int i = tid0; i < 128 * W; i += stride) {
        const int c  = i / W;
        const int k2 = i - c * W;
        const int k  = k2 * 2;
        uint32_t hw = 0, lw = 0;
        if (k < K) {
            const float* Wsrc = (c < 64) ? (Wl + c) : (Wr + (c - 64));
            const float x0 = Wsrc[k * 64];
            const float x1 = (k + 1 < K) ? Wsrc[(k + 1) * 64] : 0.f;
            const __nv_bfloat16 h0 = __float2bfloat16(x0);
            const __nv_bfloat16 h1 = __float2bfloat16(x1);
            const __nv_bfloat16 l0 = __float2bfloat16(x0 - __bfloat162float(h0));
            const __nv_bfloat16 l1 = __float2bfloat16(x1 - __bfloat162float(h1));
            __nv_bfloat162 hp; hp.x = h0; hp.y = h1;
            __nv_bfloat162 lp; lp.x = l0; lp.y = l1;
            hw = *(const uint32_t*)&hp;
            lw = *(const uint32_t*)&lp;
        }
        dh[i] = hw;
        dl[i] = lw;
    }
}

__global__ void prep_W(const float* __restrict__ W1l, const float* __restrict__ W1r,
                       const float* __restrict__ W2l, const float* __restrict__ W2r)
{
    const int tid0 = blockIdx.x * blockDim.x + threadIdx.x;
    const int stride = gridDim.x * blockDim.x;
    prep_one<IND, 92>(W1l, W1r, g_w1h, g_w1l, tid0, stride);
    prep_one<HID, 36>(W2l, W2r, g_w2h, g_w2l, tid0, stride);
}

// ---------------------------------------------------------------------------
// bf16-split tensor-core dual GEMM (ldmatrix fragments, precomputed B tiles)
// ---------------------------------------------------------------------------
template <int K, int KPAD, int SA>
__global__ void __launch_bounds__(512, 1)
gemm_mma(const float* __restrict__ A, int nrows,
         const uint32_t* __restrict__ Wh, const uint32_t* __restrict__ Wlo,
         __half* __restrict__ outL, float* __restrict__ outR)
{
    constexpr int W = SA / 2;
    constexpr int KSTEPS = KPAD / 16;

    extern __shared__ __align__(16) unsigned char smem_raw[];
    __nv_bfloat16* Ah = (__nv_bfloat16*)smem_raw;             // [128][SA]
    __nv_bfloat16* Al = Ah + 128 * SA;
    uint32_t* Bh32 = (uint32_t*)(Al + 128 * SA);              // [128][W]
    uint32_t* Bl32 = Bh32 + 128 * W;

    const int tid  = threadIdx.x;
    const int row0 = blockIdx.x * 128;
    int valid = nrows - row0; if (valid > 128) valid = 128;

    {
        int4* z = (int4*)smem_raw;
        constexpr int NZ = (2 * 128 * SA * 2) / 16;
#pragma unroll 4
        for (int i = tid; i < NZ; i += 512) z[i] = make_int4(0, 0, 0, 0);
    }

    {
        constexpr int NB4 = 128 * W / 4;
        const uint4* sh = (const uint4*)Wh;
        const uint4* sl = (const uint4*)Wlo;
        uint4* dh = (uint4*)Bh32;
        uint4* dl = (uint4*)Bl32;
#pragma unroll 2
        for (int i = tid; i < NB4; i += 512) { dh[i] = sh[i]; dl[i] = sl[i]; }
    }
    __syncthreads();

    {
        const float* Ab = A + (size_t)row0 * K;
        const int n = valid * K;
        const int n4 = n >> 2;
        for (int i4 = tid; i4 < n4; i4 += 512) {
            float4 v = ((const float4*)Ab)[i4];
            float vals[4] = {v.x, v.y, v.z, v.w};
            const int e0 = i4 << 2;
#pragma unroll
            for (int j = 0; j < 4; j++) {
                const int e = e0 + j;
                const int r = e / K;
                const int k = e - r * K;
                const float x = vals[j];
                const __nv_bfloat16 h = __float2bfloat16(x);
                Ah[r * SA + k] = h;
                Al[r * SA + k] = __float2bfloat16(x - __bfloat162float(h));
            }
        }
        for (int e = (n & ~3) + tid; e < n; e += 512) {
            const int r = e / K;
            const int k = e - r * K;
            const float x = Ab[e];
            const __nv_bfloat16 h = __float2bfloat16(x);
            Ah[r * SA + k] = h;
            Al[r * SA + k] = __float2bfloat16(x - __bfloat162float(h));
        }
    }
    __syncthreads();

    const int lane = tid & 31, wid = tid >> 5;
    const int wm = wid >> 2, wn = wid & 3;
    const int lr = lane >> 2, lc = lane & 3;

    const uint32_t AhB = (uint32_t)__cvta_generic_to_shared(Ah);
    const uint32_t AlB = (uint32_t)__cvta_generic_to_shared(Al);
    const uint32_t BhB = (uint32_t)__cvta_generic_to_shared(Bh32);
    const uint32_t BlB = (uint32_t)__cvta_generic_to_shared(Bl32);

    const uint32_t a_base = ((wm * 32 + (lane & 15)) * W + ((lane >> 4) << 2)) * 4;
    const uint32_t b_base =
        ((wn * 32 + (lane & 7) + ((lane >> 4) << 3)) * W + (((lane >> 3) & 1) << 2)) * 4;

    float acc[2][4][4];
#pragma unroll
    for (int mt = 0; mt < 2; mt++)
#pragma unroll
        for (int nt = 0; nt < 4; nt++)
#pragma unroll
            for (int q = 0; q < 4; q++) acc[mt][nt][q] = 0.f;

#pragma unroll
    for (int s = 0; s < KSTEPS; s++) {
        const uint32_t so = (s * 8) * 4;
        uint32_t ah[2][4], al[2][4];
#pragma unroll
        for (int mt = 0; mt < 2; mt++) {
            const uint32_t off = a_base + so + mt * (16 * W * 4);
            ldsm_x4(ah[mt], AhB + off);
            ldsm_x4(al[mt], AlB + off);
        }
#pragma unroll
        for (int t = 0; t < 2; t++) {
            uint32_t bh[4], bl[4];
            const uint32_t off = b_base + so + t * (16 * W * 4);
            ldsm_x4(bh, BhB + off);
            ldsm_x4(bl, BlB + off);
#pragma unroll
            for (int mt = 0; mt < 2; mt++) {
                MMA_BF16(acc[mt][2 * t],     ah[mt], bh[0], bh[1]);
                MMA_BF16(acc[mt][2 * t],     ah[mt], bl[0], bl[1]);
                MMA_BF16(acc[mt][2 * t],     al[mt], bh[0], bh[1]);
                MMA_BF16(acc[mt][2 * t + 1], ah[mt], bh[2], bh[3]);
                MMA_BF16(acc[mt][2 * t + 1], ah[mt], bl[2], bl[3]);
                MMA_BF16(acc[mt][2 * t + 1], al[mt], bh[2], bh[3]);
            }
        }
    }

#pragma unroll
    for (int mt = 0; mt < 2; mt++) {
#pragma unroll
        for (int nt = 0; nt < 4; nt++) {
            const int colb = wn * 32 + nt * 8;
            const int col = (colb + 2 * lc) & 63;
            const int row = wm * 32 + mt * 16 + lr;
            if (colb < 64) {
                if (row < valid) {
                    __half2 v = __float22half2_rn(make_float2(acc[mt][nt][0], acc[mt][nt][1]));
                    *(__half2*)(outL + (size_t)(row0 + row) * 64 + col) = v;
                }
                if (row + 8 < valid) {
                    __half2 v = __float22half2_rn(make_float2(acc[mt][nt][2], acc[mt][nt][3]));
                    *(__half2*)(outL + (size_t)(row0 + row + 8) * 64 + col) = v;
                }
            } else {
                if (row < valid) {
                    float2 v0 = make_float2(acc[mt][nt][0], acc[mt][nt][1]);
                    *(float2*)(outR + (size_t)(row0 + row) * 64 + col) = v0;
                }
                if (row + 8 < valid) {
                    float2 v1 = make_float2(acc[mt][nt][2], acc[mt][nt][3]);
                    *(float2*)(outR + (size_t)(row0 + row + 8) * 64 + col) = v1;
                }
            }
        }
    }
}

// ---------------------------------------------------------------------------
// CSR construction
// ---------------------------------------------------------------------------
__global__ void degree_vec(const int* __restrict__ ei, int E)
{
    const int q = blockIdx.x * blockDim.x + threadIdx.x;
    const int e4 = q << 2;
    if (e4 + 4 <= E) {
        const int4 d = *(const int4*)(ei + E + e4);
        atomicAdd(&g_deg[d.x], 1);
        atomicAdd(&g_deg[d.y], 1);
        atomicAdd(&g_deg[d.z], 1);
        atomicAdd(&g_deg[d.w], 1);
    } else {
        for (int e = e4; e < E; e++) atomicAdd(&g_deg[ei[E + e]], 1);
    }
}

__global__ void degree_scalar(const int* __restrict__ ei, int E)
{
    const int e = blockIdx.x * blockDim.x + threadIdx.x;
    if (e < E) atomicAdd(&g_deg[ei[E + e]], 1);
}

// Block-wide exclusive scan over 1024 elements, shfl-based (3 syncthreads)
__global__ void scan1(int n)
{
    __shared__ int wsum[32];
    const int i = blockIdx.x * 1024 + threadIdx.x;
    const int lane = threadIdx.x & 31, w = threadIdx.x >> 5;
    const int v = (i < n) ? g_deg[i] : 0;
    int inc = v;
#pragma unroll
    for (int off = 1; off < 32; off <<= 1) {
        const int t = __shfl_up_sync(0xffffffffu, inc, off);
        if (lane >= off) inc += t;
    }
    if (lane == 31) wsum[w] = inc;
    __syncthreads();
    if (w == 0) {
        const int s = wsum[lane];
        int si = s;
#pragma unroll
        for (int off = 1; off < 32; off <<= 1) {
            const int t = __shfl_up_sync(0xffffffffu, si, off);
            if (lane >= off) si += t;
        }
        wsum[lane] = si - s;               // exclusive warp offsets
        if (lane == 31) g_bsum[blockIdx.x] = si;   // block total
    }
    __syncthreads();
    if (i < n) g_off[i] = inc - v + wsum[w];       // exclusive within block
}

// Fused scan2+scan3: each block redundantly scans the <=128 block sums,
// then applies the offset and initializes cursors. blockDim = 256.
__global__ void scan23(int n, int E, int nb)
{
    __shared__ int pref[128];
    const int t = threadIdx.x;
    int v = 0;
    if (t < 128) {
        v = (t < nb) ? g_bsum[t] : 0;
        pref[t] = v;
    }
    __syncthreads();
#pragma unroll
    for (int off = 1; off < 128; off <<= 1) {
        int add = 0;
        if (t < 128 && t >= off) add = pref[t - off];
        __syncthreads();
        if (t < 128) pref[t] += add;
        __syncthreads();
    }
    if (t < 128) pref[t] -= v;   // exclusive
    __syncthreads();

    const int i = blockIdx.x * blockDim.x + t;
    if (i < n) {
        const int o = g_off[i] + pref[i >> 10];
        g_off[i] = o;
        g_cursor[i] = o;
    } else if (i == n) {
        g_off[n] = E;
    }
}

__global__ void csr_fill_vec(const int* __restrict__ ei, int E)
{
    const int q = blockIdx.x * blockDim.x + threadIdx.x;
    const int e4 = q << 2;
    if (e4 + 4 <= E) {
        const int4 s = *(const int4*)(ei + e4);
        const int4 d = *(const int4*)(ei + E + e4);
        g_csr[atomicAdd(&g_cursor[d.x], 1)] = s.x;
        g_csr[atomicAdd(&g_cursor[d.y], 1)] = s.y;
        g_csr[atomicAdd(&g_cursor[d.z], 1)] = s.z;
        g_csr[atomicAdd(&g_cursor[d.w], 1)] = s.w;
    } else {
        for (int e = e4; e < E; e++) {
            const int dst = ei[E + e];
            g_csr[atomicAdd(&g_cursor[dst], 1)] = ei[e];
        }
    }
}

__global__ void csr_fill_scalar(const int* __restrict__ ei, int E)
{
    const int e = blockIdx.x * blockDim.x + threadIdx.x;
    if (e >= E) return;
    const int dst = ei[E + e];
    g_csr[atomicAdd(&g_cursor[dst], 1)] = ei[e];
}

// ---------------------------------------------------------------------------
__device__ __forceinline__ void acc_h8(float* acc, const uint4& v)
{
    const __half2* h2 = (const __half2*)&v;
#pragma unroll
    for (int j = 0; j < 4; j++) {
        const float2 f = __half22float2(h2[j]);
        acc[2 * j]     += f.x;
        acc[2 * j + 1] += f.y;
    }
}

// ---------------------------------------------------------------------------
// Fused gather(mean) + bias + root + ReLU. 8 lanes per node, unroll 8 (MLP 8).
// ---------------------------------------------------------------------------
__global__ void __launch_bounds__(512)
gather_relu(const __half* __restrict__ y,
            const float* __restrict__ bias,
            float* __restrict__ hio, int n)
{
    const int tid = threadIdx.x;
    const int node = blockIdx.x * 64 + (tid >> 3);
    if (node >= n) return;
    const int l8 = (tid & 7) << 3;

    const int s = g_off[node];
    const int e = g_off[node + 1];

    float acc[8] = {0.f, 0.f, 0.f, 0.f, 0.f, 0.f, 0.f, 0.f};
    int p = s;
    for (; p + 8 <= e; p += 8) {
        int idx[8];
#pragma unroll
        for (int j = 0; j < 8; j++) idx[j] = g_csr[p + j];
        uint4 v[8];
#pragma unroll
        for (int j = 0; j < 8; j++) v[j] = *(const uint4*)(y + (size_t)idx[j] * 64 + l8);
#pragma unroll
        for (int j = 0; j < 8; j++) acc_h8(acc, v[j]);
    }
    for (; p + 2 <= e; p += 2) {
        const int i0 = g_csr[p], i1 = g_csr[p + 1];
        const uint4 v0 = *(const uint4*)(y + (size_t)i0 * 64 + l8);
        const uint4 v1 = *(const uint4*)(y + (size_t)i1 * 64 + l8);
        acc_h8(acc, v0); acc_h8(acc, v1);
    }
    if (p < e) {
        const uint4 v = *(const uint4*)(y + (size_t)g_csr[p] * 64 + l8);
        acc_h8(acc, v);
    }

    const float inv = 1.0f / fmaxf((float)(e - s), 1.0f);
    float* hrow = hio + (size_t)node * 64 + l8;
    const float4 r0 = *(const float4*)(hrow);
    const float4 r1 = *(const float4*)(hrow + 4);
    float rt[8] = {r0.x, r0.y, r0.z, r0.w, r1.x, r1.y, r1.z, r1.w};
    float o[8];
#pragma unroll
    for (int j = 0; j < 8; j++)
        o[j] = fmaxf(acc[j] * inv + bias[l8 + j] + rt[j], 0.f);
    *(float4*)(hrow)     = make_float4(o[0], o[1], o[2], o[3]);
    *(float4*)(hrow + 4) = make_float4(o[4], o[5], o[6], o[7]);
}

// ---------------------------------------------------------------------------
// Layer-2 gather with fused classifier
// ---------------------------------------------------------------------------
__global__ void __launch_bounds__(512)
gather_relu_cls(const __half* __restrict__ y,
                const float* __restrict__ bias,
                const float* __restrict__ root,
                const float* __restrict__ Wc,
                const float* __restrict__ bc,
                float* __restrict__ out, int n)
{
    const int tid = threadIdx.x;
    const int node = blockIdx.x * 64 + (tid >> 3);
    if (node >= n) return;
    const int l8 = (tid & 7) << 3;

    const int s = g_off[node];
    const int e = g_off[node + 1];

    float acc[8] = {0.f, 0.f, 0.f, 0.f, 0.f, 0.f, 0.f, 0.f};
    int p = s;
    for (; p + 8 <= e; p += 8) {
        int idx[8];
#pragma unroll
        for (int j = 0; j < 8; j++) idx[j] = g_csr[p + j];
        uint4 v[8];
#pragma unroll
        for (int j = 0; j < 8; j++) v[j] = *(const uint4*)(y + (size_t)idx[j] * 64 + l8);
#pragma unroll
        for (int j = 0; j < 8; j++) acc_h8(acc, v[j]);
    }
    for (; p + 2 <= e; p += 2) {
        const int i0 = g_csr[p], i1 = g_csr[p + 1];
        const uint4 v0 = *(const uint4*)(y + (size_t)i0 * 64 + l8);
        const uint4 v1 = *(const uint4*)(y + (size_t)i1 * 64 + l8);
        acc_h8(acc, v0); acc_h8(acc, v1);
    }
    if (p < e) {
        const uint4 v = *(const uint4*)(y + (size_t)g_csr[p] * 64 + l8);
        acc_h8(acc, v);
    }

    const float inv = 1.0f / fmaxf((float)(e - s), 1.0f);
    const float* rrow = root + (size_t)node * 64 + l8;
    const float4 r0 = *(const float4*)(rrow);
    const float4 r1 = *(const float4*)(rrow + 4);
    float rt[8] = {r0.x, r0.y, r0.z, r0.w, r1.x, r1.y, r1.z, r1.w};

    float p0 = 0.f, p1 = 0.f;
#pragma unroll
    for (int j = 0; j < 8; j++) {
        const float h = fmaxf(acc[j] * inv + bias[l8 + j] + rt[j], 0.f);
        p0 += h * Wc[(l8 + j) * 2];
        p1 += h * Wc[(l8 + j) * 2 + 1];
    }
#pragma unroll
    for (int off = 4; off > 0; off >>= 1) {
        p0 += __shfl_xor_sync(0xffffffffu, p0, off, 8);
        p1 += __shfl_xor_sync(0xffffffffu, p1, off, 8);
    }
    if ((tid & 7) == 0) {
        out[(size_t)node * 2 + 0] = p0 + bc[0];
        out[(size_t)node * 2 + 1] = p1 + bc[1];
    }
}

// ---------------------------------------------------------------------------
extern "C" void kernel_launch(void* const* d_in, const int* in_sizes, int n_in,
                              void* d_out, int out_size)
{
    const float* x   = (const float*)d_in[0];
    const int*   ei  = (const int*)  d_in[1];
    const float* W1l = (const float*)d_in[2];
    const float* b1  = (const float*)d_in[3];
    const float* W1r = (const float*)d_in[4];
    const float* W2l = (const float*)d_in[5];
    const float* b2  = (const float*)d_in[6];
    const float* W2r = (const float*)d_in[7];
    const float* Wc  = (const float*)d_in[8];
    const float* bc  = (const float*)d_in[9];

    const int N = in_sizes[0] / IND;
    const int E = in_sizes[1] / 2;
    float* out = (float*)d_out;

    void *yp_v, *hp_v, *degp_v;
    void *w1h_v, *w1l_v, *w2h_v, *w2l_v;
    cudaGetSymbolAddress(&yp_v,   g_y);
    cudaGetSymbolAddress(&hp_v,   g_h);
    cudaGetSymbolAddress(&degp_v, g_deg);
    cudaGetSymbolAddress(&w1h_v,  g_w1h);
    cudaGetSymbolAddress(&w1l_v,  g_w1l);
    cudaGetSymbolAddress(&w2h_v,  g_w2h);
    cudaGetSymbolAddress(&w2l_v,  g_w2l);
    __half* yp = (__half*)yp_v;
    float*  hp = (float*)hp_v;

    constexpr int SMEM1 = 1024 * 184;
    constexpr int SMEM2 = 1024 * 72;
    cudaFuncSetAttribute(gemm_mma<IND, 176, 184>,
                         cudaFuncAttributeMaxDynamicSharedMemorySize, SMEM1);
    cudaFuncSetAttribute(gemm_mma<HID, 64, 72>,
                         cudaFuncAttributeMaxDynamicSharedMemorySize, SMEM2);

    static cudaStream_t s_side = nullptr;
    static cudaEvent_t ev_fork = nullptr, ev_prep = nullptr, ev_join = nullptr;
    if (s_side == nullptr) {
        cudaStreamCreateWithFlags(&s_side, cudaStreamNonBlocking);
        cudaEventCreateWithFlags(&ev_fork, cudaEventDisableTiming);
        cudaEventCreateWithFlags(&ev_prep, cudaEventDisableTiming);
        cudaEventCreateWithFlags(&ev_join, cudaEventDisableTiming);
    }

    const int gemm_blocks   = (N + 127) / 128;
    const int scan_blocks   = (N + 1023) / 1024;
    const int gather_blocks = (N + 63) / 64;
    const bool e_aligned    = ((E & 3) == 0);

    // ---- Fork: weight prep + CSR build on side stream ----
    cudaEventRecord(ev_fork, 0);
    cudaStreamWaitEvent(s_side, ev_fork, 0);
    prep_W<<<64, 256, 0, s_side>>>(W1l, W1r, W2l, W2r);
    cudaEventRecord(ev_prep, s_side);
    cudaMemsetAsync(degp_v, 0, (size_t)N * sizeof(int), s_side);
    if (e_aligned) {
        const int q = E >> 2;
        degree_vec<<<(q + 255) / 256, 256, 0, s_side>>>(ei, E);
    } else {
        degree_scalar<<<(E + 255) / 256, 256, 0, s_side>>>(ei, E);
    }
    scan1<<<scan_blocks, 1024, 0, s_side>>>(N);
    scan23<<<(N + 256) / 256, 256, 0, s_side>>>(N, E, scan_blocks);
    if (e_aligned) {
        const int q = E >> 2;
        csr_fill_vec<<<(q + 255) / 256, 256, 0, s_side>>>(ei, E);
    } else {
        csr_fill_scalar<<<(E + 255) / 256, 256, 0, s_side>>>(ei, E);
    }
    cudaEventRecord(ev_join, s_side);

    // ---- Main: Layer-1 GEMM (waits only for weight tiles) ----
    cudaStreamWaitEvent(0, ev_prep, 0);
    gemm_mma<IND, 176, 184><<<gemm_blocks, 512, SMEM1>>>(
        x, N, (const uint32_t*)w1h_v, (const uint32_t*)w1l_v, yp, hp);

    // ---- Join CSR, then gathers / layer 2 ----
    cudaStreamWaitEvent(0, ev_join, 0);
    gather_relu<<<gather_blocks, 512>>>(yp, b1, hp, N);

    gemm_mma<HID, 64, 72><<<gemm_blocks, 512, SMEM2>>>(
        hp, N, (const uint32_t*)w2h_v, (const uint32_t*)w2l_v, yp, hp);
    gather_relu_cls<<<gather_blocks, 512>>>(yp, b2, hp, Wc, bc, out, N);
}

// round 7
// speedup vs baseline: 1.2218x; 1.2218x over previous
#include <cuda_runtime.h>
#include <cuda_bf16.h>
#include <cuda_fp16.h>
#include <stdint.h>

#define NN     100000
#define EE     1600000
#define IND    165
#define HID    64

// Scratch (device globals — no allocation allowed)
__device__ __align__(16) unsigned short g_y[NN * HID];  // fp16 message buffer
__device__ float g_h[NN * HID];       // root path / layer output (fp32)
__device__ int   g_deg[NN];           // in-degree (int)
__device__ int   g_off[NN + 1];       // CSR row offsets
__device__ int   g_cursor[NN];        // bucket-fill cursors
__device__ int   g_csr[EE];           // CSR column (src) indices
__device__ int   g_bsum[128];         // scan block sums

// Precomputed bf16-split B in MMA-fragment order: [wn][s][t][lane] -> uint4
// Layer1: 4*11*2*32 = 2816 uint4 per array; Layer2: 4*4*2*32 = 1024 uint4.
__device__ __align__(16) uint4 g_bf1h[2816];
__device__ __align__(16) uint4 g_bf1l[2816];
__device__ __align__(16) uint4 g_bf2h[1024];
__device__ __align__(16) uint4 g_bf2l[1024];

// ---------------------------------------------------------------------------
#define MMA_BF16(d, a, b0, b1)                                                 \
  asm volatile(                                                                \
      "mma.sync.aligned.m16n8k16.row.col.f32.bf16.bf16.f32 "                   \
      "{%0,%1,%2,%3},{%4,%5,%6,%7},{%8,%9},{%0,%1,%2,%3};"                     \
      : "+f"(d[0]), "+f"(d[1]), "+f"(d[2]), "+f"(d[3])                         \
      : "r"(a[0]), "r"(a[1]), "r"(a[2]), "r"(a[3]), "r"(b0), "r"(b1))

__device__ __forceinline__ void ldsm_x4(uint32_t* r, uint32_t addr)
{
    asm volatile("ldmatrix.sync.aligned.m8n8.x4.shared.b16 {%0,%1,%2,%3}, [%4];"
                 : "=r"(r[0]), "=r"(r[1]), "=r"(r[2]), "=r"(r[3]) : "r"(addr));
}

// ---------------------------------------------------------------------------
// Weight fragment precompute: for MMA covering cols [n0,n0+8) k-chunk [k0,k0+16)
// thread `lane` holds b0 = pack(W[k0+2*(lane&3)][n0+(lane>>2)], W[k0+2*(lane&3)+1][...])
// and b1 = same with k+8. uint4 = {b0(n0), b1(n0), b0(n0+8), b1(n0+8)}.
// ---------------------------------------------------------------------------
__device__ __forceinline__ uint32_t pack_pair_hi(const float* Wl, const float* Wr,
                                                 int n, int k, int K, bool lo)
{
    const float* Wsrc = (n < 64) ? (Wl + n) : (Wr + (n - 64));
    float x0 = (k < K)     ? Wsrc[k * 64]       : 0.f;
    float x1 = (k + 1 < K) ? Wsrc[(k + 1) * 64] : 0.f;
    __nv_bfloat16 h0 = __float2bfloat16(x0);
    __nv_bfloat16 h1 = __float2bfloat16(x1);
    if (lo) {
        h0 = __float2bfloat16(x0 - __bfloat162float(h0));
        h1 = __float2bfloat16(x1 - __bfloat162float(h1));
    }
    __nv_bfloat162 p; p.x = h0; p.y = h1;
    return *(const uint32_t*)&p;
}

template <int K, int KSTEPS>
__device__ __forceinline__ void prep_frag(const float* Wl, const float* Wr,
                                          uint4* fh, uint4* fl, int tid0, int stride)
{
    const int total = 4 * KSTEPS * 2 * 32;
    for (int i = tid0; i < total; i += stride) {
        const int lane = i & 31;
        const int t    = (i >> 5) & 1;
        const int s    = (i >> 6) % KSTEPS;
        const int wn   = (i >> 6) / KSTEPS;
        const int n0   = wn * 32 + t * 16 + (lane >> 2);
        const int k0   = s * 16 + 2 * (lane & 3);
        uint4 h, l;
        h.x = pack_pair_hi(Wl, Wr, n0,     k0,     K, false);
        h.y = pack_pair_hi(Wl, Wr, n0,     k0 + 8, K, false);
        h.z = pack_pair_hi(Wl, Wr, n0 + 8, k0,     K, false);
        h.w = pack_pair_hi(Wl, Wr, n0 + 8, k0 + 8, K, false);
        l.x = pack_pair_hi(Wl, Wr, n0,     k0,     K, true);
        l.y = pack_pair_hi(Wl, Wr, n0,     k0 + 8, K, true);
        l.z = pack_pair_hi(Wl, Wr, n0 + 8, k0,     K, true);
        l.w = pack_pair_hi(Wl, Wr, n0 + 8, k0 + 8, K, true);
        fh[i] = h;
        fl[i] = l;
    }
}

// Also zeros g_deg (removes a separate memset launch)
__global__ void prep_W(const float* __restrict__ W1l, const float* __restrict__ W1r,
                       const float* __restrict__ W2l, const float* __restrict__ W2r,
                       int n)
{
    const int tid0 = blockIdx.x * blockDim.x + threadIdx.x;
    const int stride = gridDim.x * blockDim.x;
    prep_frag<IND, 11>(W1l, W1r, g_bf1h, g_bf1l, tid0, stride);
    prep_frag<HID, 4>(W2l, W2r, g_bf2h, g_bf2l, tid0, stride);
    for (int i = tid0; i < n; i += stride) g_deg[i] = 0;
}

// ---------------------------------------------------------------------------
// bf16-split tensor-core dual GEMM. A staged in smem (hi/lo), B fragments
// loaded straight from global (L1-resident, coalesced 16B per lane).
// ---------------------------------------------------------------------------
template <int K, int KPAD, int SA>
__global__ void __launch_bounds__(512, 2)
gemm_mma(const float* __restrict__ A, int nrows,
         const uint4* __restrict__ Bfh, const uint4* __restrict__ Bfl,
         __half* __restrict__ outL, float* __restrict__ outR)
{
    constexpr int W = SA / 2;
    constexpr int KSTEPS = KPAD / 16;

    extern __shared__ __align__(16) unsigned char smem_raw[];
    __nv_bfloat16* Ah = (__nv_bfloat16*)smem_raw;             // [128][SA]
    __nv_bfloat16* Al = Ah + 128 * SA;

    const int tid  = threadIdx.x;
    const int row0 = blockIdx.x * 128;
    int valid = nrows - row0; if (valid > 128) valid = 128;

    // ---- zero only what ldmatrix can read and staging won't cover ----
    if (valid == 128) {
        if (KPAD > K) {
            constexpr int PADW = (KPAD > K) ? (KPAD - K) : 1;
            const __nv_bfloat16 z = __float2bfloat16(0.f);
            for (int i = tid; i < 128 * PADW; i += 512) {
                const int r = i / PADW;
                const int c = K + (i - r * PADW);
                Ah[r * SA + c] = z;
                Al[r * SA + c] = z;
            }
        }
    } else {
        int4* zp = (int4*)smem_raw;
        constexpr int NZ = (2 * 128 * SA * 2) / 16;
#pragma unroll 4
        for (int i = tid; i < NZ; i += 512) zp[i] = make_int4(0, 0, 0, 0);
    }
    if (valid < 128) __syncthreads();   // full zero must precede staging

    // ---- stage A: contiguous float4 reads, bf16 split scalar stores ----
    {
        const float* Ab = A + (size_t)row0 * K;
        const int n = valid * K;
        const int n4 = n >> 2;
        for (int i4 = tid; i4 < n4; i4 += 512) {
            float4 v = ((const float4*)Ab)[i4];
            float vals[4] = {v.x, v.y, v.z, v.w};
            const int e0 = i4 << 2;
#pragma unroll
            for (int j = 0; j < 4; j++) {
                const int e = e0 + j;
                const int r = e / K;
                const int k = e - r * K;
                const float x = vals[j];
                const __nv_bfloat16 h = __float2bfloat16(x);
                Ah[r * SA + k] = h;
                Al[r * SA + k] = __float2bfloat16(x - __bfloat162float(h));
            }
        }
        for (int e = (n & ~3) + tid; e < n; e += 512) {
            const int r = e / K;
            const int k = e - r * K;
            const float x = Ab[e];
            const __nv_bfloat16 h = __float2bfloat16(x);
            Ah[r * SA + k] = h;
            Al[r * SA + k] = __float2bfloat16(x - __bfloat162float(h));
        }
    }
    __syncthreads();

    // ---- MMA mainloop ----
    const int lane = tid & 31, wid = tid >> 5;
    const int wm = wid >> 2, wn = wid & 3;
    const int lr = lane >> 2, lc = lane & 3;

    const uint32_t AhB = (uint32_t)__cvta_generic_to_shared(Ah);
    const uint32_t AlB = (uint32_t)__cvta_generic_to_shared(Al);
    const uint32_t a_base = ((wm * 32 + (lane & 15)) * W + ((lane >> 4) << 2)) * 4;
    const uint4* bfh = Bfh + (size_t)wn * KSTEPS * 2 * 32 + lane;
    const uint4* bfl = Bfl + (size_t)wn * KSTEPS * 2 * 32 + lane;

    float acc[2][4][4];
#pragma unroll
    for (int mt = 0; mt < 2; mt++)
#pragma unroll
        for (int nt = 0; nt < 4; nt++)
#pragma unroll
            for (int q = 0; q < 4; q++) acc[mt][nt][q] = 0.f;

#pragma unroll
    for (int s = 0; s < KSTEPS; s++) {
        const uint32_t so = (s * 8) * 4;
        uint32_t ah[2][4], al[2][4];
#pragma unroll
        for (int mt = 0; mt < 2; mt++) {
            const uint32_t off = a_base + so + mt * (16 * W * 4);
            ldsm_x4(ah[mt], AhB + off);
            ldsm_x4(al[mt], AlB + off);
        }
#pragma unroll
        for (int t = 0; t < 2; t++) {
            const int fi = (s * 2 + t) * 32;
            const uint4 bh = bfh[fi];
            const uint4 bl = bfl[fi];
#pragma unroll
            for (int mt = 0; mt < 2; mt++) {
                MMA_BF16(acc[mt][2 * t],     ah[mt], bh.x, bh.y);
                MMA_BF16(acc[mt][2 * t],     ah[mt], bl.x, bl.y);
                MMA_BF16(acc[mt][2 * t],     al[mt], bh.x, bh.y);
                MMA_BF16(acc[mt][2 * t + 1], ah[mt], bh.z, bh.w);
                MMA_BF16(acc[mt][2 * t + 1], ah[mt], bl.z, bl.w);
                MMA_BF16(acc[mt][2 * t + 1], al[mt], bh.z, bh.w);
            }
        }
    }

    // ---- epilogue ----
#pragma unroll
    for (int mt = 0; mt < 2; mt++) {
#pragma unroll
        for (int nt = 0; nt < 4; nt++) {
            const int colb = wn * 32 + nt * 8;
            const int col = (colb + 2 * lc) & 63;
            const int row = wm * 32 + mt * 16 + lr;
            if (colb < 64) {
                if (row < valid) {
                    __half2 v = __float22half2_rn(make_float2(acc[mt][nt][0], acc[mt][nt][1]));
                    *(__half2*)(outL + (size_t)(row0 + row) * 64 + col) = v;
                }
                if (row + 8 < valid) {
                    __half2 v = __float22half2_rn(make_float2(acc[mt][nt][2], acc[mt][nt][3]));
                    *(__half2*)(outL + (size_t)(row0 + row + 8) * 64 + col) = v;
                }
            } else {
                if (row < valid) {
                    float2 v0 = make_float2(acc[mt][nt][0], acc[mt][nt][1]);
                    *(float2*)(outR + (size_t)(row0 + row) * 64 + col) = v0;
                }
                if (row + 8 < valid) {
                    float2 v1 = make_float2(acc[mt][nt][2], acc[mt][nt][3]);
                    *(float2*)(outR + (size_t)(row0 + row + 8) * 64 + col) = v1;
                }
            }
        }
    }
}

// ---------------------------------------------------------------------------
// CSR construction
// ---------------------------------------------------------------------------
__global__ void degree_vec(const int* __restrict__ ei, int E)
{
    const int q = blockIdx.x * blockDim.x + threadIdx.x;
    const int e4 = q << 2;
    if (e4 + 4 <= E) {
        const int4 d = *(const int4*)(ei + E + e4);
        atomicAdd(&g_deg[d.x], 1);
        atomicAdd(&g_deg[d.y], 1);
        atomicAdd(&g_deg[d.z], 1);
        atomicAdd(&g_deg[d.w], 1);
    } else {
        for (int e = e4; e < E; e++) atomicAdd(&g_deg[ei[E + e]], 1);
    }
}

__global__ void degree_scalar(const int* __restrict__ ei, int E)
{
    const int e = blockIdx.x * blockDim.x + threadIdx.x;
    if (e < E) atomicAdd(&g_deg[ei[E + e]], 1);
}

__global__ void scan1(int n)
{
    __shared__ int wsum[32];
    const int i = blockIdx.x * 1024 + threadIdx.x;
    const int lane = threadIdx.x & 31, w = threadIdx.x >> 5;
    const int v = (i < n) ? g_deg[i] : 0;
    int inc = v;
#pragma unroll
    for (int off = 1; off < 32; off <<= 1) {
        const int t = __shfl_up_sync(0xffffffffu, inc, off);
        if (lane >= off) inc += t;
    }
    if (lane == 31) wsum[w] = inc;
    __syncthreads();
    if (w == 0) {
        const int s = wsum[lane];
        int si = s;
#pragma unroll
        for (int off = 1; off < 32; off <<= 1) {
            const int t = __shfl_up_sync(0xffffffffu, si, off);
            if (lane >= off) si += t;
        }
        wsum[lane] = si - s;
        if (lane == 31) g_bsum[blockIdx.x] = si;
    }
    __syncthreads();
    if (i < n) g_off[i] = inc - v + wsum[w];
}

__global__ void scan23(int n, int E, int nb)
{
    __shared__ int pref[128];
    const int t = threadIdx.x;
    int v = 0;
    if (t < 128) {
        v = (t < nb) ? g_bsum[t] : 0;
        pref[t] = v;
    }
    __syncthreads();
#pragma unroll
    for (int off = 1; off < 128; off <<= 1) {
        int add = 0;
        if (t < 128 && t >= off) add = pref[t - off];
        __syncthreads();
        if (t < 128) pref[t] += add;
        __syncthreads();
    }
    if (t < 128) pref[t] -= v;
    __syncthreads();

    const int i = blockIdx.x * blockDim.x + t;
    if (i < n) {
        const int o = g_off[i] + pref[i >> 10];
        g_off[i] = o;
        g_cursor[i] = o;
    } else if (i == n) {
        g_off[n] = E;
    }
}

__global__ void csr_fill_vec(const int* __restrict__ ei, int E)
{
    const int q = blockIdx.x * blockDim.x + threadIdx.x;
    const int e4 = q << 2;
    if (e4 + 4 <= E) {
        const int4 s = *(const int4*)(ei + e4);
        const int4 d = *(const int4*)(ei + E + e4);
        g_csr[atomicAdd(&g_cursor[d.x], 1)] = s.x;
        g_csr[atomicAdd(&g_cursor[d.y], 1)] = s.y;
        g_csr[atomicAdd(&g_cursor[d.z], 1)] = s.z;
        g_csr[atomicAdd(&g_cursor[d.w], 1)] = s.w;
    } else {
        for (int e = e4; e < E; e++) {
            const int dst = ei[E + e];
            g_csr[atomicAdd(&g_cursor[dst], 1)] = ei[e];
        }
    }
}

__global__ void csr_fill_scalar(const int* __restrict__ ei, int E)
{
    const int e = blockIdx.x * blockDim.x + threadIdx.x;
    if (e >= E) return;
    const int dst = ei[E + e];
    g_csr[atomicAdd(&g_cursor[dst], 1)] = ei[e];
}

// ---------------------------------------------------------------------------
__device__ __forceinline__ void acc_h8(float* acc, const uint4& v)
{
    const __half2* h2 = (const __half2*)&v;
#pragma unroll
    for (int j = 0; j < 4; j++) {
        const float2 f = __half22float2(h2[j]);
        acc[2 * j]     += f.x;
        acc[2 * j + 1] += f.y;
    }
}

// ---------------------------------------------------------------------------
// Fused gather(mean) + bias + root + ReLU. 8 lanes per node (R5-proven shape).
// ---------------------------------------------------------------------------
__global__ void gather_relu(const __half* __restrict__ y,
                            const float* __restrict__ bias,
                            float* __restrict__ hio, int n)
{
    const int tid = threadIdx.x;
    const int node = blockIdx.x * 32 + (tid >> 3);
    if (node >= n) return;
    const int l8 = (tid & 7) << 3;

    const int s = g_off[node];
    const int e = g_off[node + 1];

    float acc[8] = {0.f, 0.f, 0.f, 0.f, 0.f, 0.f, 0.f, 0.f};
    int p = s;
    for (; p + 4 <= e; p += 4) {
        const int s0 = g_csr[p], s1 = g_csr[p + 1], s2 = g_csr[p + 2], s3 = g_csr[p + 3];
        const uint4 v0 = *(const uint4*)(y + (size_t)s0 * 64 + l8);
        const uint4 v1 = *(const uint4*)(y + (size_t)s1 * 64 + l8);
        const uint4 v2 = *(const uint4*)(y + (size_t)s2 * 64 + l8);
        const uint4 v3 = *(const uint4*)(y + (size_t)s3 * 64 + l8);
        acc_h8(acc, v0); acc_h8(acc, v1); acc_h8(acc, v2); acc_h8(acc, v3);
    }
    for (; p < e; p++) {
        const uint4 v = *(const uint4*)(y + (size_t)g_csr[p] * 64 + l8);
        acc_h8(acc, v);
    }

    const float inv = 1.0f / fmaxf((float)(e - s), 1.0f);
    float* hrow = hio + (size_t)node * 64 + l8;
    const float4 r0 = *(const float4*)(hrow);
    const float4 r1 = *(const float4*)(hrow + 4);
    float rt[8] = {r0.x, r0.y, r0.z, r0.w, r1.x, r1.y, r1.z, r1.w};
    float o[8];
#pragma unroll
    for (int j = 0; j < 8; j++)
        o[j] = fmaxf(acc[j] * inv + bias[l8 + j] + rt[j], 0.f);
    *(float4*)(hrow)     = make_float4(o[0], o[1], o[2], o[3]);
    *(float4*)(hrow + 4) = make_float4(o[4], o[5], o[6], o[7]);
}

// ---------------------------------------------------------------------------
// Layer-2 gather with fused classifier
// ---------------------------------------------------------------------------
__global__ void gather_relu_cls(const __half* __restrict__ y,
                                const float* __restrict__ bias,
                                const float* __restrict__ root,
                                const float* __restrict__ Wc,
                                const float* __restrict__ bc,
                                float* __restrict__ out, int n)
{
    const int tid = threadIdx.x;
    const int node = blockIdx.x * 32 + (tid >> 3);
    if (node >= n) return;
    const int l8 = (tid & 7) << 3;

    const int s = g_off[node];
    const int e = g_off[node + 1];

    float acc[8] = {0.f, 0.f, 0.f, 0.f, 0.f, 0.f, 0.f, 0.f};
    int p = s;
    for (; p + 4 <= e; p += 4) {
        const int s0 = g_csr[p], s1 = g_csr[p + 1], s2 = g_csr[p + 2], s3 = g_csr[p + 3];
        const uint4 v0 = *(const uint4*)(y + (size_t)s0 * 64 + l8);
        const uint4 v1 = *(const uint4*)(y + (size_t)s1 * 64 + l8);
        const uint4 v2 = *(const uint4*)(y + (size_t)s2 * 64 + l8);
        const uint4 v3 = *(const uint4*)(y + (size_t)s3 * 64 + l8);
        acc_h8(acc, v0); acc_h8(acc, v1); acc_h8(acc, v2); acc_h8(acc, v3);
    }
    for (; p < e; p++) {
        const uint4 v = *(const uint4*)(y + (size_t)g_csr[p] * 64 + l8);
        acc_h8(acc, v);
    }

    const float inv = 1.0f / fmaxf((float)(e - s), 1.0f);
    const float* rrow = root + (size_t)node * 64 + l8;
    const float4 r0 = *(const float4*)(rrow);
    const float4 r1 = *(const float4*)(rrow + 4);
    float rt[8] = {r0.x, r0.y, r0.z, r0.w, r1.x, r1.y, r1.z, r1.w};

    float p0 = 0.f, p1 = 0.f;
#pragma unroll
    for (int j = 0; j < 8; j++) {
        const float h = fmaxf(acc[j] * inv + bias[l8 + j] + rt[j], 0.f);
        p0 += h * Wc[(l8 + j) * 2];
        p1 += h * Wc[(l8 + j) * 2 + 1];
    }
#pragma unroll
    for (int off = 4; off > 0; off >>= 1) {
        p0 += __shfl_xor_sync(0xffffffffu, p0, off, 8);
        p1 += __shfl_xor_sync(0xffffffffu, p1, off, 8);
    }
    if ((tid & 7) == 0) {
        out[(size_t)node * 2 + 0] = p0 + bc[0];
        out[(size_t)node * 2 + 1] = p1 + bc[1];
    }
}

// ---------------------------------------------------------------------------
extern "C" void kernel_launch(void* const* d_in, const int* in_sizes, int n_in,
                              void* d_out, int out_size)
{
    const float* x   = (const float*)d_in[0];
    const int*   ei  = (const int*)  d_in[1];
    const float* W1l = (const float*)d_in[2];
    const float* b1  = (const float*)d_in[3];
    const float* W1r = (const float*)d_in[4];
    const float* W2l = (const float*)d_in[5];
    const float* b2  = (const float*)d_in[6];
    const float* W2r = (const float*)d_in[7];
    const float* Wc  = (const float*)d_in[8];
    const float* bc  = (const float*)d_in[9];

    const int N = in_sizes[0] / IND;
    const int E = in_sizes[1] / 2;
    float* out = (float*)d_out;

    void *yp_v, *hp_v;
    void *b1h_v, *b1l_v, *b2h_v, *b2l_v;
    cudaGetSymbolAddress(&yp_v,  g_y);
    cudaGetSymbolAddress(&hp_v,  g_h);
    cudaGetSymbolAddress(&b1h_v, g_bf1h);
    cudaGetSymbolAddress(&b1l_v, g_bf1l);
    cudaGetSymbolAddress(&b2h_v, g_bf2h);
    cudaGetSymbolAddress(&b2l_v, g_bf2l);
    __half* yp = (__half*)yp_v;
    float*  hp = (float*)hp_v;

    constexpr int SMEM1 = 128 * 184 * 2 * 2;   // 94208 B (A hi/lo only)
    constexpr int SMEM2 = 128 * 72 * 2 * 2;    // 36864 B
    cudaFuncSetAttribute(gemm_mma<IND, 176, 184>,
                         cudaFuncAttributeMaxDynamicSharedMemorySize, SMEM1);
    cudaFuncSetAttribute(gemm_mma<HID, 64, 72>,
                         cudaFuncAttributeMaxDynamicSharedMemorySize, SMEM2);

    static cudaStream_t s_side = nullptr;
    static cudaEvent_t ev_fork = nullptr, ev_prep = nullptr, ev_join = nullptr;
    if (s_side == nullptr) {
        cudaStreamCreateWithFlags(&s_side, cudaStreamNonBlocking);
        cudaEventCreateWithFlags(&ev_fork, cudaEventDisableTiming);
        cudaEventCreateWithFlags(&ev_prep, cudaEventDisableTiming);
        cudaEventCreateWithFlags(&ev_join, cudaEventDisableTiming);
    }

    const int gemm_blocks   = (N + 127) / 128;
    const int scan_blocks   = (N + 1023) / 1024;
    const int gather_blocks = (N + 31) / 32;
    const bool e_aligned    = ((E & 3) == 0);

    // ---- Fork: weight fragments (+deg zero) + CSR build on side stream ----
    cudaEventRecord(ev_fork, 0);
    cudaStreamWaitEvent(s_side, ev_fork, 0);
    prep_W<<<64, 256, 0, s_side>>>(W1l, W1r, W2l, W2r, N);
    cudaEventRecord(ev_prep, s_side);
    if (e_aligned) {
        const int q = E >> 2;
        degree_vec<<<(q + 255) / 256, 256, 0, s_side>>>(ei, E);
    } else {
        degree_scalar<<<(E + 255) / 256, 256, 0, s_side>>>(ei, E);
    }
    scan1<<<scan_blocks, 1024, 0, s_side>>>(N);
    scan23<<<(N + 256) / 256, 256, 0, s_side>>>(N, E, scan_blocks);
    if (e_aligned) {
        const int q = E >> 2;
        csr_fill_vec<<<(q + 255) / 256, 256, 0, s_side>>>(ei, E);
    } else {
        csr_fill_scalar<<<(E + 255) / 256, 256, 0, s_side>>>(ei, E);
    }
    cudaEventRecord(ev_join, s_side);

    // ---- Main: Layer-1 GEMM (waits only for weight fragments) ----
    cudaStreamWaitEvent(0, ev_prep, 0);
    gemm_mma<IND, 176, 184><<<gemm_blocks, 512, SMEM1>>>(
        x, N, (const uint4*)b1h_v, (const uint4*)b1l_v, yp, hp);

    // ---- Join CSR, then gathers / layer 2 ----
    cudaStreamWaitEvent(0, ev_join, 0);
    gather_relu<<<gather_blocks, 256>>>(yp, b1, hp, N);

    gemm_mma<HID, 64, 72><<<gemm_blocks, 512, SMEM2>>>(
        hp, N, (const uint4*)b2h_v, (const uint4*)b2l_v, yp, hp);
    gather_relu_cls<<<gather_blocks, 256>>>(yp, b2, hp, Wc, bc, out, N);
}